// round 14
// baseline (speedup 1.0000x reference)
#include <cuda_runtime.h>
#include <cuda_bf16.h>
#include <cstdint>

#define NN   100000
#define NE   800000
#define IND  128
#define HID  256
#define OUTD 40
#define NB1  98   // ceil(NN/1024)

// ---------------- scratch (static __device__ per harness rules) ----------------
__device__ int   g_cnt[NN];
__device__ int   g_rowptr[NN + 1];
__device__ int   g_cursor[NN];
__device__ int   g_col[NE];
__device__ float g_dinv[NN];
__device__ int   g_bsum[NB1];
__device__ int   g_boff[NB1];
__device__ __nv_bfloat16 g_xah[(size_t)NN * IND];   // aggregated input, bf16 hi
__device__ __nv_bfloat16 g_xal[(size_t)NN * IND];   // aggregated input, bf16 lo
__device__ __nv_bfloat16 g_w1th[(size_t)HID * IND]; // W1^T [n][k] bf16 hi
__device__ __nv_bfloat16 g_w1tl[(size_t)HID * IND]; // W1^T [n][k] bf16 lo
__device__ __nv_bfloat16 g_a1h[(size_t)NN * HID];   // layer-1 activations hi
__device__ __nv_bfloat16 g_a1l[(size_t)NN * HID];   // layer-1 activations lo
__device__ __nv_bfloat16 g_w2th[(size_t)OUTD * HID]; // W2^T [n][k] bf16 hi
__device__ __nv_bfloat16 g_w2tl[(size_t)OUTD * HID]; // W2^T [n][k] bf16 lo
__device__ float g_h2t[(size_t)NN * OUTD]; // (a1@W2)*dinv[row]

// ---------------- degree / CSR construction ----------------
__global__ void k_zero() {
    int i = blockIdx.x * blockDim.x + threadIdx.x;
    if (i < NN) g_cnt[i] = 0;
}

__global__ void k_count(const int* __restrict__ dst) {
    int e = blockIdx.x * blockDim.x + threadIdx.x;
    if (e < NE) atomicAdd(&g_cnt[dst[e]], 1);
}

__global__ void k_scan_reduce() {
    int i = blockIdx.x * 1024 + threadIdx.x;
    int v = (i < NN) ? g_cnt[i] : 0;
    #pragma unroll
    for (int d = 16; d; d >>= 1) v += __shfl_down_sync(0xffffffffu, v, d);
    __shared__ int sm[32];
    int lane = threadIdx.x & 31, wid = threadIdx.x >> 5;
    if (lane == 0) sm[wid] = v;
    __syncthreads();
    if (wid == 0) {
        int w = sm[lane];
        #pragma unroll
        for (int d = 16; d; d >>= 1) w += __shfl_down_sync(0xffffffffu, w, d);
        if (lane == 0) g_bsum[blockIdx.x] = w;
    }
}

__global__ void k_scan_mid() {
    __shared__ int sm[NB1];
    int t = threadIdx.x;
    if (t < NB1) sm[t] = g_bsum[t];
    __syncthreads();
    if (t == 0) {
        int run = 0;
        for (int i = 0; i < NB1; i++) { int c = sm[i]; sm[i] = run; run += c; }
        g_rowptr[NN] = run;
    }
    __syncthreads();
    if (t < NB1) g_boff[t] = sm[t];
}

__global__ void k_scan_final() {
    int i = blockIdx.x * 1024 + threadIdx.x;
    int lane = threadIdx.x & 31, wid = threadIdx.x >> 5;
    int c = (i < NN) ? g_cnt[i] : 0;
    int v = c;
    #pragma unroll
    for (int d = 1; d < 32; d <<= 1) {
        int t = __shfl_up_sync(0xffffffffu, v, d);
        if (lane >= d) v += t;
    }
    __shared__ int ws[32];
    if (lane == 31) ws[wid] = v;
    __syncthreads();
    if (wid == 0) {
        int w = ws[lane];
        #pragma unroll
        for (int d = 1; d < 32; d <<= 1) {
            int t = __shfl_up_sync(0xffffffffu, w, d);
            if (lane >= d) w += t;
        }
        ws[lane] = w;
    }
    __syncthreads();
    int woff = wid ? ws[wid - 1] : 0;
    int excl = v - c + woff + g_boff[blockIdx.x];
    if (i < NN) {
        g_rowptr[i] = excl;
        g_cursor[i] = excl;
        g_dinv[i]   = rsqrtf((float)(c + 1));  // +1 self-loop, deg >= 1
    }
}

__global__ void k_fill(const int* __restrict__ src, const int* __restrict__ dst) {
    int e = blockIdx.x * blockDim.x + threadIdx.x;
    if (e < NE) {
        int d = dst[e];
        int p = atomicAdd(&g_cursor[d], 1);
        g_col[p] = src[e];
    }
}

// ---------------- W1 / W2 transpose + bf16 split ----------------
__global__ void k_convw1(const float* __restrict__ W1) {
    int idx = blockIdx.x * 256 + threadIdx.x;   // 0..32767
    int n = idx & 255, k = idx >> 8;
    float v = W1[(size_t)k * HID + n];
    __nv_bfloat16 h = __float2bfloat16(v);
    g_w1th[(size_t)n * IND + k] = h;
    g_w1tl[(size_t)n * IND + k] = __float2bfloat16(v - __bfloat162float(h));
}

__global__ void k_convw2(const float* __restrict__ W2) {
    int idx = blockIdx.x * 256 + threadIdx.x;   // 0..10239
    int k = idx & 255, n = idx >> 8;            // n 0..39
    float v = W2[(size_t)k * OUTD + n];
    __nv_bfloat16 h = __float2bfloat16(v);
    g_w2th[(size_t)n * HID + k] = h;
    g_w2tl[(size_t)n * HID + k] = __float2bfloat16(v - __bfloat162float(h));
}

// ---------------- aggX: xa[d]=dinv[d]*(sum dinv[s]x[s] + dinv[d]x[d]), bf16 split out --
__global__ __launch_bounds__(256) void k_aggx(const float* __restrict__ x) {
    int gw = (blockIdx.x * 256 + threadIdx.x) >> 5;
    int lane = threadIdx.x & 31;
    if (gw >= NN) return;

    const float4* x4 = (const float4*)x;
    float dg = g_dinv[gw];
    float4 xs = x4[(size_t)gw * 32 + lane];
    float4 acc;
    acc.x = dg * xs.x; acc.y = dg * xs.y; acc.z = dg * xs.z; acc.w = dg * xs.w;

    int beg = g_rowptr[gw], end = g_rowptr[gw + 1];
    for (int e = beg; e < end; e++) {
        int s = g_col[e];
        float ds = g_dinv[s];
        float4 v = x4[(size_t)s * 32 + lane];
        acc.x = fmaf(ds, v.x, acc.x);
        acc.y = fmaf(ds, v.y, acc.y);
        acc.z = fmaf(ds, v.z, acc.z);
        acc.w = fmaf(ds, v.w, acc.w);
    }

    float ox = dg * acc.x, oy = dg * acc.y, oz = dg * acc.z, ow = dg * acc.w;
    __nv_bfloat16 hx = __float2bfloat16(ox), hy = __float2bfloat16(oy);
    __nv_bfloat16 hz = __float2bfloat16(oz), hw = __float2bfloat16(ow);
    __nv_bfloat162 h01, h23, l01, l23;
    h01.x = hx; h01.y = hy; h23.x = hz; h23.y = hw;
    l01.x = __float2bfloat16(ox - __bfloat162float(hx));
    l01.y = __float2bfloat16(oy - __bfloat162float(hy));
    l23.x = __float2bfloat16(oz - __bfloat162float(hz));
    l23.y = __float2bfloat16(ow - __bfloat162float(hw));
    size_t base = (size_t)gw * IND + lane * 4;
    *(__nv_bfloat162*)(g_xah + base)     = h01;
    *(__nv_bfloat162*)(g_xah + base + 2) = h23;
    *(__nv_bfloat162*)(g_xal + base)     = l01;
    *(__nv_bfloat162*)(g_xal + base + 2) = l23;
}

#define MMA16816(c, a, b)                                                       \
    asm volatile("mma.sync.aligned.m16n8k16.row.col.f32.bf16.bf16.f32 "         \
        "{%0,%1,%2,%3}, {%4,%5,%6,%7}, {%8,%9}, {%0,%1,%2,%3};"                 \
        : "+f"((c)[0]), "+f"((c)[1]), "+f"((c)[2]), "+f"((c)[3])                \
        : "r"((a)[0]), "r"((a)[1]), "r"((a)[2]), "r"((a)[3]),                   \
          "r"((b)[0]), "r"((b)[1]))

// ---------------- GEMM1 (mma.sync bf16 split): a1 = relu(xa @ W1 + b1) --------
// CTA 128x128 tile (grid.y=2 over N=256). K=128 in two 64-chunks in SMEM.
// 8 warps: 2 (m) x 4 (n); warp tile 64x32 = 4x4 m16n8k16 tiles; 3 mma per tile.
// Epilogue emits a1 as bf16 hi/lo pairs for GEMM2's mma path.
#define G1_STRIDE 72                              // 64 + 8 pad (bf16 units)
#define G1_ARR    (128 * G1_STRIDE)               // 9216 bf16 = 18432 B
#define G1_SMEM   (4 * G1_ARR * 2)                // 73728 B

__global__ __launch_bounds__(256, 2) void k_gemm1_mma(const float* __restrict__ b1) {
    extern __shared__ __nv_bfloat16 smb[];
    __nv_bfloat16* AH = smb;
    __nv_bfloat16* AL = smb + G1_ARR;
    __nv_bfloat16* BH = smb + 2 * G1_ARR;
    __nv_bfloat16* BL = smb + 3 * G1_ARR;

    const int tid = threadIdx.x;
    const int wid = tid >> 5, lane = tid & 31;
    const int g = lane >> 2, tg = lane & 3;
    const int wm = wid >> 2, wn = wid & 3;       // warp tile: (wm*64, wn*32)
    const int m0 = blockIdx.x * 128;
    const int n0 = blockIdx.y * 128;

    float acc[4][4][4];
    #pragma unroll
    for (int mi = 0; mi < 4; mi++)
        #pragma unroll
        for (int ni = 0; ni < 4; ni++)
            #pragma unroll
            for (int q = 0; q < 4; q++) acc[mi][ni][q] = 0.f;

    for (int kc = 0; kc < 2; kc++) {
        #pragma unroll
        for (int i = 0; i < 4; i++) {
            int idx = tid + i * 256;             // 0..1023
            int r = idx >> 3, c8 = idx & 7;
            size_t goff = (size_t)(m0 + r) * IND + kc * 64 + c8 * 8;
            uint4 z = make_uint4(0, 0, 0, 0);
            bool ok = (m0 + r) < NN;
            *(uint4*)(AH + r * G1_STRIDE + c8 * 8) = ok ? *(const uint4*)(g_xah + goff) : z;
            *(uint4*)(AL + r * G1_STRIDE + c8 * 8) = ok ? *(const uint4*)(g_xal + goff) : z;
            size_t boff = (size_t)(n0 + r) * IND + kc * 64 + c8 * 8;
            *(uint4*)(BH + r * G1_STRIDE + c8 * 8) = *(const uint4*)(g_w1th + boff);
            *(uint4*)(BL + r * G1_STRIDE + c8 * 8) = *(const uint4*)(g_w1tl + boff);
        }
        __syncthreads();

        #pragma unroll
        for (int ks = 0; ks < 4; ks++) {
            int k0 = ks * 16;
            uint32_t af[4][4], bh[4][2], bl[4][2];
            #pragma unroll
            for (int ni = 0; ni < 4; ni++) {
                const __nv_bfloat16* p = BH + (wn * 32 + ni * 8 + g) * G1_STRIDE + k0 + 2 * tg;
                bh[ni][0] = *(const uint32_t*)(p);
                bh[ni][1] = *(const uint32_t*)(p + 8);
                const __nv_bfloat16* q = BL + (wn * 32 + ni * 8 + g) * G1_STRIDE + k0 + 2 * tg;
                bl[ni][0] = *(const uint32_t*)(q);
                bl[ni][1] = *(const uint32_t*)(q + 8);
            }
            #pragma unroll
            for (int mi = 0; mi < 4; mi++) {
                const __nv_bfloat16* p = AH + (wm * 64 + mi * 16 + g) * G1_STRIDE + k0 + 2 * tg;
                af[mi][0] = *(const uint32_t*)(p);
                af[mi][1] = *(const uint32_t*)(p + 8 * G1_STRIDE);
                af[mi][2] = *(const uint32_t*)(p + 8);
                af[mi][3] = *(const uint32_t*)(p + 8 * G1_STRIDE + 8);
            }
            #pragma unroll
            for (int mi = 0; mi < 4; mi++)
                #pragma unroll
                for (int ni = 0; ni < 4; ni++) {
                    MMA16816(acc[mi][ni], af[mi], bh[ni]);
                    MMA16816(acc[mi][ni], af[mi], bl[ni]);
                }
            #pragma unroll
            for (int mi = 0; mi < 4; mi++) {
                const __nv_bfloat16* p = AL + (wm * 64 + mi * 16 + g) * G1_STRIDE + k0 + 2 * tg;
                af[mi][0] = *(const uint32_t*)(p);
                af[mi][1] = *(const uint32_t*)(p + 8 * G1_STRIDE);
                af[mi][2] = *(const uint32_t*)(p + 8);
                af[mi][3] = *(const uint32_t*)(p + 8 * G1_STRIDE + 8);
            }
            #pragma unroll
            for (int mi = 0; mi < 4; mi++)
                #pragma unroll
                for (int ni = 0; ni < 4; ni++)
                    MMA16816(acc[mi][ni], af[mi], bh[ni]);
        }
        __syncthreads();
    }

    // ---- epilogue: bias + relu, split to bf16 hi/lo ----
    #pragma unroll
    for (int ni = 0; ni < 4; ni++) {
        int col = n0 + wn * 32 + ni * 8 + 2 * tg;
        float bz0 = __ldg(b1 + col), bz1 = __ldg(b1 + col + 1);
        #pragma unroll
        for (int mi = 0; mi < 4; mi++) {
            #pragma unroll
            for (int half = 0; half < 2; half++) {
                int row = m0 + wm * 64 + mi * 16 + g + half * 8;
                if (row < NN) {
                    float v0 = fmaxf(acc[mi][ni][half * 2]     + bz0, 0.f);
                    float v1 = fmaxf(acc[mi][ni][half * 2 + 1] + bz1, 0.f);
                    __nv_bfloat16 h0 = __float2bfloat16(v0);
                    __nv_bfloat16 h1 = __float2bfloat16(v1);
                    __nv_bfloat162 hh, ll;
                    hh.x = h0; hh.y = h1;
                    ll.x = __float2bfloat16(v0 - __bfloat162float(h0));
                    ll.y = __float2bfloat16(v1 - __bfloat162float(h1));
                    size_t off = (size_t)row * HID + col;
                    *(__nv_bfloat162*)(g_a1h + off) = hh;
                    *(__nv_bfloat162*)(g_a1l + off) = ll;
                }
            }
        }
    }
}

// ---------------- GEMM2 (mma.sync bf16 split): h2t = (a1 @ W2) * dinv ---------
// CTA 256 rows x 40 cols. B (W2^T hi/lo) fully K-resident; A staged in K=32 chunks.
// 8 warps x 32 rows; warp: 2 m16 x 5 n8 tiles; 3-pass split.
#define G2_ASTR  40                               // 32 + 8 pad
#define G2_BSTR  264                              // 256 + 8 pad
#define G2_AARR  (256 * G2_ASTR)                  // 10240 bf16
#define G2_BARR  (OUTD * G2_BSTR)                 // 10560 bf16
#define G2_SMEM  ((2 * G2_AARR + 2 * G2_BARR) * 2)  // 83200 B

__global__ __launch_bounds__(256, 2) void k_gemm2_mma() {
    extern __shared__ __nv_bfloat16 smb2[];
    __nv_bfloat16* AH = smb2;
    __nv_bfloat16* AL = smb2 + G2_AARR;
    __nv_bfloat16* BH = smb2 + 2 * G2_AARR;
    __nv_bfloat16* BL = smb2 + 2 * G2_AARR + G2_BARR;

    const int tid = threadIdx.x;
    const int wid = tid >> 5, lane = tid & 31;
    const int g = lane >> 2, tg = lane & 3;
    const int m0 = blockIdx.x * 256;

    // ---- load full B (40 x 256, hi+lo): 1280 uint4 chunks, 5 per thread ----
    #pragma unroll
    for (int i = 0; i < 5; i++) {
        int idx = tid + i * 256;                 // 0..1279
        int r = idx >> 5, c8 = idx & 31;         // r: n 0..39, c8: k-chunk
        size_t goff = (size_t)r * HID + c8 * 8;
        *(uint4*)(BH + r * G2_BSTR + c8 * 8) = *(const uint4*)(g_w2th + goff);
        *(uint4*)(BL + r * G2_BSTR + c8 * 8) = *(const uint4*)(g_w2tl + goff);
    }

    float acc[2][5][4];
    #pragma unroll
    for (int mi = 0; mi < 2; mi++)
        #pragma unroll
        for (int ni = 0; ni < 5; ni++)
            #pragma unroll
            for (int q = 0; q < 4; q++) acc[mi][ni][q] = 0.f;

    for (int kc = 0; kc < 8; kc++) {
        // ---- stage A chunk: 256 rows x 32 k = 1024 uint4, 4 per thread ----
        #pragma unroll
        for (int i = 0; i < 4; i++) {
            int idx = tid + i * 256;             // 0..1023
            int r = idx >> 2, c8 = idx & 3;
            size_t goff = (size_t)(m0 + r) * HID + kc * 32 + c8 * 8;
            uint4 z = make_uint4(0, 0, 0, 0);
            bool ok = (m0 + r) < NN;
            *(uint4*)(AH + r * G2_ASTR + c8 * 8) = ok ? *(const uint4*)(g_a1h + goff) : z;
            *(uint4*)(AL + r * G2_ASTR + c8 * 8) = ok ? *(const uint4*)(g_a1l + goff) : z;
        }
        __syncthreads();

        #pragma unroll
        for (int ks = 0; ks < 2; ks++) {
            int k0l = ks * 16;                   // within A chunk
            int k0g = kc * 32 + ks * 16;         // within full-K B
            uint32_t af[2][4], bh[5][2], bl[5][2];
            #pragma unroll
            for (int ni = 0; ni < 5; ni++) {
                const __nv_bfloat16* p = BH + (ni * 8 + g) * G2_BSTR + k0g + 2 * tg;
                bh[ni][0] = *(const uint32_t*)(p);
                bh[ni][1] = *(const uint32_t*)(p + 8);
                const __nv_bfloat16* q = BL + (ni * 8 + g) * G2_BSTR + k0g + 2 * tg;
                bl[ni][0] = *(const uint32_t*)(q);
                bl[ni][1] = *(const uint32_t*)(q + 8);
            }
            #pragma unroll
            for (int mi = 0; mi < 2; mi++) {
                const __nv_bfloat16* p = AH + (wid * 32 + mi * 16 + g) * G2_ASTR + k0l + 2 * tg;
                af[mi][0] = *(const uint32_t*)(p);
                af[mi][1] = *(const uint32_t*)(p + 8 * G2_ASTR);
                af[mi][2] = *(const uint32_t*)(p + 8);
                af[mi][3] = *(const uint32_t*)(p + 8 * G2_ASTR + 8);
            }
            #pragma unroll
            for (int mi = 0; mi < 2; mi++)
                #pragma unroll
                for (int ni = 0; ni < 5; ni++) {
                    MMA16816(acc[mi][ni], af[mi], bh[ni]);
                    MMA16816(acc[mi][ni], af[mi], bl[ni]);
                }
            #pragma unroll
            for (int mi = 0; mi < 2; mi++) {
                const __nv_bfloat16* p = AL + (wid * 32 + mi * 16 + g) * G2_ASTR + k0l + 2 * tg;
                af[mi][0] = *(const uint32_t*)(p);
                af[mi][1] = *(const uint32_t*)(p + 8 * G2_ASTR);
                af[mi][2] = *(const uint32_t*)(p + 8);
                af[mi][3] = *(const uint32_t*)(p + 8 * G2_ASTR + 8);
            }
            #pragma unroll
            for (int mi = 0; mi < 2; mi++)
                #pragma unroll
                for (int ni = 0; ni < 5; ni++)
                    MMA16816(acc[mi][ni], af[mi], bh[ni]);
        }
        __syncthreads();
    }

    // ---- epilogue: * dinv[row], float2 stores to g_h2t ----
    #pragma unroll
    for (int mi = 0; mi < 2; mi++) {
        #pragma unroll
        for (int half = 0; half < 2; half++) {
            int row = m0 + wid * 32 + mi * 16 + g + half * 8;
            if (row < NN) {
                float di = g_dinv[row];
                #pragma unroll
                for (int ni = 0; ni < 5; ni++) {
                    float2 o;
                    o.x = acc[mi][ni][half * 2]     * di;
                    o.y = acc[mi][ni][half * 2 + 1] * di;
                    *(float2*)(g_h2t + (size_t)row * OUTD + ni * 8 + 2 * tg) = o;
                }
            }
        }
    }
}

// ---------------- agg2 + bias + log_softmax ----------------
__global__ __launch_bounds__(256) void k_agg2(const float* __restrict__ b2,
                                              float* __restrict__ out) {
    int gw = (blockIdx.x * 256 + threadIdx.x) >> 5;
    int lane = threadIdx.x & 31;
    if (gw >= NN) return;
    bool hi = lane < 8;

    const float* self = g_h2t + (size_t)gw * OUTD;
    float a0 = self[lane];
    float a1v = hi ? self[32 + lane] : 0.f;

    int beg = g_rowptr[gw], end = g_rowptr[gw + 1];
    for (int e = beg; e < end; e++) {
        int s = g_col[e];
        const float* p = g_h2t + (size_t)s * OUTD;
        a0 += p[lane];
        if (hi) a1v += p[32 + lane];
    }

    float di = g_dinv[gw];
    float z0 = fmaf(di, a0, b2[lane]);
    float z1 = hi ? fmaf(di, a1v, b2[32 + lane]) : -3.4e38f;

    float mx = fmaxf(z0, z1);
    #pragma unroll
    for (int d = 16; d; d >>= 1) mx = fmaxf(mx, __shfl_xor_sync(0xffffffffu, mx, d));
    float s0 = expf(z0 - mx) + (hi ? expf(z1 - mx) : 0.f);
    #pragma unroll
    for (int d = 16; d; d >>= 1) s0 += __shfl_xor_sync(0xffffffffu, s0, d);
    float lse = mx + logf(s0);

    out[(size_t)gw * OUTD + lane] = z0 - lse;
    if (hi) out[(size_t)gw * OUTD + 32 + lane] = z1 - lse;
}

// ---------------- launch ----------------
extern "C" void kernel_launch(void* const* d_in, const int* in_sizes, int n_in,
                              void* d_out, int out_size) {
    const float* x  = (const float*)d_in[0];
    const int*   ei = (const int*)d_in[1];
    const float* W1 = (const float*)d_in[2];
    const float* b1 = (const float*)d_in[3];
    const float* W2 = (const float*)d_in[4];
    const float* b2 = (const float*)d_in[5];
    const int* src = ei;
    const int* dst = ei + NE;
    float* out = (float*)d_out;

    // Idempotent, capture-safe (not stream ops); no static guard per harness rules.
    cudaFuncSetAttribute(k_gemm1_mma, cudaFuncAttributeMaxDynamicSharedMemorySize, G1_SMEM);
    cudaFuncSetAttribute(k_gemm2_mma, cudaFuncAttributeMaxDynamicSharedMemorySize, G2_SMEM);

    k_zero<<<(NN + 255) / 256, 256>>>();
    k_count<<<(NE + 255) / 256, 256>>>(dst);
    k_scan_reduce<<<NB1, 1024>>>();
    k_scan_mid<<<1, 128>>>();
    k_scan_final<<<NB1, 1024>>>();
    k_fill<<<(NE + 255) / 256, 256>>>(src, dst);

    k_convw1<<<128, 256>>>(W1);
    k_convw2<<<40, 256>>>(W2);
    k_aggx<<<(NN * 32 + 255) / 256, 256>>>(x);
    k_gemm1_mma<<<dim3((NN + 127) / 128, 2), 256, G1_SMEM>>>(b1);
    k_gemm2_mma<<<(NN + 255) / 256, 256, G2_SMEM>>>();
    k_agg2<<<(NN * 32 + 255) / 256, 256>>>(b2, out);
}

// round 15
// speedup vs baseline: 1.0223x; 1.0223x over previous
#include <cuda_runtime.h>
#include <cuda_bf16.h>
#include <cstdint>

#define NN   100000
#define NE   800000
#define IND  128
#define HID  256
#define OUTD 40
#define NB1  98   // ceil(NN/1024)

// ---------------- scratch (static __device__ per harness rules) ----------------
__device__ int   g_cnt[NN];
__device__ int   g_rowptr[NN + 1];
__device__ int   g_cursor[NN];
__device__ int   g_col[NE];
__device__ float g_dinv[NN];
__device__ int   g_bsum[NB1];
__device__ int   g_arrive;
__device__ __nv_bfloat16 g_xah[(size_t)NN * IND];   // aggregated input, bf16 hi
__device__ __nv_bfloat16 g_xal[(size_t)NN * IND];   // aggregated input, bf16 lo
__device__ __nv_bfloat16 g_w1th[(size_t)HID * IND]; // W1^T [n][k] bf16 hi
__device__ __nv_bfloat16 g_w1tl[(size_t)HID * IND]; // W1^T [n][k] bf16 lo
__device__ __nv_bfloat16 g_a1h[(size_t)NN * HID];   // layer-1 activations hi
__device__ __nv_bfloat16 g_a1l[(size_t)NN * HID];   // layer-1 activations lo
__device__ __nv_bfloat16 g_w2th[(size_t)OUTD * HID]; // W2^T [n][k] bf16 hi
__device__ __nv_bfloat16 g_w2tl[(size_t)OUTD * HID]; // W2^T [n][k] bf16 lo
__device__ float g_h2t[(size_t)NN * OUTD]; // (a1@W2)*dinv[row]

// ---------------- fused init: zero counters + W1/W2 transpose-split ----------
__global__ __launch_bounds__(256) void k_init(const float* __restrict__ W1,
                                              const float* __restrict__ W2) {
    int i = blockIdx.x * 256 + threadIdx.x;
    if (i < NN) g_cnt[i] = 0;
    if (i == 0) g_arrive = 0;
    if (i < HID * IND) {                        // 32768: W1 transpose+split
        int n = i & 255, k = i >> 8;
        float v = W1[(size_t)k * HID + n];
        __nv_bfloat16 h = __float2bfloat16(v);
        g_w1th[(size_t)n * IND + k] = h;
        g_w1tl[(size_t)n * IND + k] = __float2bfloat16(v - __bfloat162float(h));
    }
    if (i < OUTD * HID) {                       // 10240: W2 transpose+split
        int k = i & 255, n = i >> 8;
        float v = W2[(size_t)k * OUTD + n];
        __nv_bfloat16 h = __float2bfloat16(v);
        g_w2th[(size_t)n * HID + k] = h;
        g_w2tl[(size_t)n * HID + k] = __float2bfloat16(v - __bfloat162float(h));
    }
}

__global__ void k_count(const int* __restrict__ dst) {
    int e = blockIdx.x * blockDim.x + threadIdx.x;
    if (e < NE) atomicAdd(&g_cnt[dst[e]], 1);
}

// ---------------- fused scan: single-wave grid handshake --------------------
// 98 blocks (< 148 SMs => all co-resident). Each block: intra-block scan,
// publish block total, spin on arrival counter, then add cross-block prefix.
__global__ __launch_bounds__(1024) void k_scanf() {
    const int b = blockIdx.x, t = threadIdx.x;
    const int i = b * 1024 + t;
    const int lane = t & 31, wid = t >> 5;

    int c = (i < NN) ? g_cnt[i] : 0;
    int v = c;
    #pragma unroll
    for (int d = 1; d < 32; d <<= 1) {
        int tt = __shfl_up_sync(0xffffffffu, v, d);
        if (lane >= d) v += tt;
    }
    __shared__ int ws[32];
    if (lane == 31) ws[wid] = v;
    __syncthreads();
    if (wid == 0) {
        int w = ws[lane];
        #pragma unroll
        for (int d = 1; d < 32; d <<= 1) {
            int tt = __shfl_up_sync(0xffffffffu, w, d);
            if (lane >= d) w += tt;
        }
        ws[lane] = w;
    }
    __syncthreads();
    const int woff = wid ? ws[wid - 1] : 0;
    const int incl = v + woff;          // inclusive prefix within block
    const int btotal = ws[31];

    if (t == 0) {
        g_bsum[b] = btotal;
        __threadfence();
        atomicAdd(&g_arrive, 1);
        while (atomicAdd(&g_arrive, 0) < NB1) { }
    }
    __syncthreads();

    __shared__ int sm[NB1];
    __shared__ int boffs;
    if (t < NB1) sm[t] = g_bsum[t];
    __syncthreads();
    if (t == 0) {
        int run = 0;
        for (int j = 0; j < b; j++) run += sm[j];
        boffs = run;
        if (b == NB1 - 1) g_rowptr[NN] = run + btotal;
    }
    __syncthreads();

    if (i < NN) {
        int excl = incl - c + boffs;
        g_rowptr[i] = excl;
        g_cursor[i] = excl;
        g_dinv[i]   = rsqrtf((float)(c + 1));  // +1 self-loop, deg >= 1
    }
}

__global__ void k_fill(const int* __restrict__ src, const int* __restrict__ dst) {
    int e = blockIdx.x * blockDim.x + threadIdx.x;
    if (e < NE) {
        int d = dst[e];
        int p = atomicAdd(&g_cursor[d], 1);
        g_col[p] = src[e];
    }
}

// ---------------- aggX: xa[d]=dinv[d]*(sum dinv[s]x[s] + dinv[d]x[d]), bf16 split out --
__global__ __launch_bounds__(256) void k_aggx(const float* __restrict__ x) {
    int gw = (blockIdx.x * 256 + threadIdx.x) >> 5;
    int lane = threadIdx.x & 31;
    if (gw >= NN) return;

    const float4* x4 = (const float4*)x;
    float dg = g_dinv[gw];
    float4 xs = x4[(size_t)gw * 32 + lane];
    float4 acc;
    acc.x = dg * xs.x; acc.y = dg * xs.y; acc.z = dg * xs.z; acc.w = dg * xs.w;

    int beg = g_rowptr[gw], end = g_rowptr[gw + 1];
    for (int e = beg; e < end; e++) {
        int s = g_col[e];
        float ds = g_dinv[s];
        float4 v = x4[(size_t)s * 32 + lane];
        acc.x = fmaf(ds, v.x, acc.x);
        acc.y = fmaf(ds, v.y, acc.y);
        acc.z = fmaf(ds, v.z, acc.z);
        acc.w = fmaf(ds, v.w, acc.w);
    }

    float ox = dg * acc.x, oy = dg * acc.y, oz = dg * acc.z, ow = dg * acc.w;
    __nv_bfloat16 hx = __float2bfloat16(ox), hy = __float2bfloat16(oy);
    __nv_bfloat16 hz = __float2bfloat16(oz), hw = __float2bfloat16(ow);
    __nv_bfloat162 h01, h23, l01, l23;
    h01.x = hx; h01.y = hy; h23.x = hz; h23.y = hw;
    l01.x = __float2bfloat16(ox - __bfloat162float(hx));
    l01.y = __float2bfloat16(oy - __bfloat162float(hy));
    l23.x = __float2bfloat16(oz - __bfloat162float(hz));
    l23.y = __float2bfloat16(ow - __bfloat162float(hw));
    size_t base = (size_t)gw * IND + lane * 4;
    *(__nv_bfloat162*)(g_xah + base)     = h01;
    *(__nv_bfloat162*)(g_xah + base + 2) = h23;
    *(__nv_bfloat162*)(g_xal + base)     = l01;
    *(__nv_bfloat162*)(g_xal + base + 2) = l23;
}

#define MMA16816(c, a, b)                                                       \
    asm volatile("mma.sync.aligned.m16n8k16.row.col.f32.bf16.bf16.f32 "         \
        "{%0,%1,%2,%3}, {%4,%5,%6,%7}, {%8,%9}, {%0,%1,%2,%3};"                 \
        : "+f"((c)[0]), "+f"((c)[1]), "+f"((c)[2]), "+f"((c)[3])                \
        : "r"((a)[0]), "r"((a)[1]), "r"((a)[2]), "r"((a)[3]),                   \
          "r"((b)[0]), "r"((b)[1]))

// ---------------- GEMM1 (mma.sync bf16 split): a1 = relu(xa @ W1 + b1) --------
#define G1_STRIDE 72                              // 64 + 8 pad (bf16 units)
#define G1_ARR    (128 * G1_STRIDE)               // 9216 bf16 = 18432 B
#define G1_SMEM   (4 * G1_ARR * 2)                // 73728 B

__global__ __launch_bounds__(256, 2) void k_gemm1_mma(const float* __restrict__ b1) {
    extern __shared__ __nv_bfloat16 smb[];
    __nv_bfloat16* AH = smb;
    __nv_bfloat16* AL = smb + G1_ARR;
    __nv_bfloat16* BH = smb + 2 * G1_ARR;
    __nv_bfloat16* BL = smb + 3 * G1_ARR;

    const int tid = threadIdx.x;
    const int wid = tid >> 5, lane = tid & 31;
    const int g = lane >> 2, tg = lane & 3;
    const int wm = wid >> 2, wn = wid & 3;       // warp tile: (wm*64, wn*32)
    const int m0 = blockIdx.x * 128;
    const int n0 = blockIdx.y * 128;

    float acc[4][4][4];
    #pragma unroll
    for (int mi = 0; mi < 4; mi++)
        #pragma unroll
        for (int ni = 0; ni < 4; ni++)
            #pragma unroll
            for (int q = 0; q < 4; q++) acc[mi][ni][q] = 0.f;

    for (int kc = 0; kc < 2; kc++) {
        #pragma unroll
        for (int i = 0; i < 4; i++) {
            int idx = tid + i * 256;             // 0..1023
            int r = idx >> 3, c8 = idx & 7;
            size_t goff = (size_t)(m0 + r) * IND + kc * 64 + c8 * 8;
            uint4 z = make_uint4(0, 0, 0, 0);
            bool ok = (m0 + r) < NN;
            *(uint4*)(AH + r * G1_STRIDE + c8 * 8) = ok ? *(const uint4*)(g_xah + goff) : z;
            *(uint4*)(AL + r * G1_STRIDE + c8 * 8) = ok ? *(const uint4*)(g_xal + goff) : z;
            size_t boff = (size_t)(n0 + r) * IND + kc * 64 + c8 * 8;
            *(uint4*)(BH + r * G1_STRIDE + c8 * 8) = *(const uint4*)(g_w1th + boff);
            *(uint4*)(BL + r * G1_STRIDE + c8 * 8) = *(const uint4*)(g_w1tl + boff);
        }
        __syncthreads();

        #pragma unroll
        for (int ks = 0; ks < 4; ks++) {
            int k0 = ks * 16;
            uint32_t af[4][4], bh[4][2], bl[4][2];
            #pragma unroll
            for (int ni = 0; ni < 4; ni++) {
                const __nv_bfloat16* p = BH + (wn * 32 + ni * 8 + g) * G1_STRIDE + k0 + 2 * tg;
                bh[ni][0] = *(const uint32_t*)(p);
                bh[ni][1] = *(const uint32_t*)(p + 8);
                const __nv_bfloat16* q = BL + (wn * 32 + ni * 8 + g) * G1_STRIDE + k0 + 2 * tg;
                bl[ni][0] = *(const uint32_t*)(q);
                bl[ni][1] = *(const uint32_t*)(q + 8);
            }
            #pragma unroll
            for (int mi = 0; mi < 4; mi++) {
                const __nv_bfloat16* p = AH + (wm * 64 + mi * 16 + g) * G1_STRIDE + k0 + 2 * tg;
                af[mi][0] = *(const uint32_t*)(p);
                af[mi][1] = *(const uint32_t*)(p + 8 * G1_STRIDE);
                af[mi][2] = *(const uint32_t*)(p + 8);
                af[mi][3] = *(const uint32_t*)(p + 8 * G1_STRIDE + 8);
            }
            #pragma unroll
            for (int mi = 0; mi < 4; mi++)
                #pragma unroll
                for (int ni = 0; ni < 4; ni++) {
                    MMA16816(acc[mi][ni], af[mi], bh[ni]);
                    MMA16816(acc[mi][ni], af[mi], bl[ni]);
                }
            #pragma unroll
            for (int mi = 0; mi < 4; mi++) {
                const __nv_bfloat16* p = AL + (wm * 64 + mi * 16 + g) * G1_STRIDE + k0 + 2 * tg;
                af[mi][0] = *(const uint32_t*)(p);
                af[mi][1] = *(const uint32_t*)(p + 8 * G1_STRIDE);
                af[mi][2] = *(const uint32_t*)(p + 8);
                af[mi][3] = *(const uint32_t*)(p + 8 * G1_STRIDE + 8);
            }
            #pragma unroll
            for (int mi = 0; mi < 4; mi++)
                #pragma unroll
                for (int ni = 0; ni < 4; ni++)
                    MMA16816(acc[mi][ni], af[mi], bh[ni]);
        }
        __syncthreads();
    }

    // ---- epilogue: bias + relu, split to bf16 hi/lo ----
    #pragma unroll
    for (int ni = 0; ni < 4; ni++) {
        int col = n0 + wn * 32 + ni * 8 + 2 * tg;
        float bz0 = __ldg(b1 + col), bz1 = __ldg(b1 + col + 1);
        #pragma unroll
        for (int mi = 0; mi < 4; mi++) {
            #pragma unroll
            for (int half = 0; half < 2; half++) {
                int row = m0 + wm * 64 + mi * 16 + g + half * 8;
                if (row < NN) {
                    float v0 = fmaxf(acc[mi][ni][half * 2]     + bz0, 0.f);
                    float v1 = fmaxf(acc[mi][ni][half * 2 + 1] + bz1, 0.f);
                    __nv_bfloat16 h0 = __float2bfloat16(v0);
                    __nv_bfloat16 h1 = __float2bfloat16(v1);
                    __nv_bfloat162 hh, ll;
                    hh.x = h0; hh.y = h1;
                    ll.x = __float2bfloat16(v0 - __bfloat162float(h0));
                    ll.y = __float2bfloat16(v1 - __bfloat162float(h1));
                    size_t off = (size_t)row * HID + col;
                    *(__nv_bfloat162*)(g_a1h + off) = hh;
                    *(__nv_bfloat162*)(g_a1l + off) = ll;
                }
            }
        }
    }
}

// ---------------- GEMM2 (mma.sync bf16 split): h2t = (a1 @ W2) * dinv ---------
#define G2_ASTR  40                               // 32 + 8 pad
#define G2_BSTR  264                              // 256 + 8 pad
#define G2_AARR  (256 * G2_ASTR)                  // 10240 bf16
#define G2_BARR  (OUTD * G2_BSTR)                 // 10560 bf16
#define G2_SMEM  ((2 * G2_AARR + 2 * G2_BARR) * 2)  // 83200 B

__global__ __launch_bounds__(256, 2) void k_gemm2_mma() {
    extern __shared__ __nv_bfloat16 smb2[];
    __nv_bfloat16* AH = smb2;
    __nv_bfloat16* AL = smb2 + G2_AARR;
    __nv_bfloat16* BH = smb2 + 2 * G2_AARR;
    __nv_bfloat16* BL = smb2 + 2 * G2_AARR + G2_BARR;

    const int tid = threadIdx.x;
    const int wid = tid >> 5, lane = tid & 31;
    const int g = lane >> 2, tg = lane & 3;
    const int m0 = blockIdx.x * 256;

    #pragma unroll
    for (int i = 0; i < 5; i++) {
        int idx = tid + i * 256;                 // 0..1279
        int r = idx >> 5, c8 = idx & 31;
        size_t goff = (size_t)r * HID + c8 * 8;
        *(uint4*)(BH + r * G2_BSTR + c8 * 8) = *(const uint4*)(g_w2th + goff);
        *(uint4*)(BL + r * G2_BSTR + c8 * 8) = *(const uint4*)(g_w2tl + goff);
    }

    float acc[2][5][4];
    #pragma unroll
    for (int mi = 0; mi < 2; mi++)
        #pragma unroll
        for (int ni = 0; ni < 5; ni++)
            #pragma unroll
            for (int q = 0; q < 4; q++) acc[mi][ni][q] = 0.f;

    for (int kc = 0; kc < 8; kc++) {
        #pragma unroll
        for (int i = 0; i < 4; i++) {
            int idx = tid + i * 256;             // 0..1023
            int r = idx >> 2, c8 = idx & 3;
            size_t goff = (size_t)(m0 + r) * HID + kc * 32 + c8 * 8;
            uint4 z = make_uint4(0, 0, 0, 0);
            bool ok = (m0 + r) < NN;
            *(uint4*)(AH + r * G2_ASTR + c8 * 8) = ok ? *(const uint4*)(g_a1h + goff) : z;
            *(uint4*)(AL + r * G2_ASTR + c8 * 8) = ok ? *(const uint4*)(g_a1l + goff) : z;
        }
        __syncthreads();

        #pragma unroll
        for (int ks = 0; ks < 2; ks++) {
            int k0l = ks * 16;
            int k0g = kc * 32 + ks * 16;
            uint32_t af[2][4], bh[5][2], bl[5][2];
            #pragma unroll
            for (int ni = 0; ni < 5; ni++) {
                const __nv_bfloat16* p = BH + (ni * 8 + g) * G2_BSTR + k0g + 2 * tg;
                bh[ni][0] = *(const uint32_t*)(p);
                bh[ni][1] = *(const uint32_t*)(p + 8);
                const __nv_bfloat16* q = BL + (ni * 8 + g) * G2_BSTR + k0g + 2 * tg;
                bl[ni][0] = *(const uint32_t*)(q);
                bl[ni][1] = *(const uint32_t*)(q + 8);
            }
            #pragma unroll
            for (int mi = 0; mi < 2; mi++) {
                const __nv_bfloat16* p = AH + (wid * 32 + mi * 16 + g) * G2_ASTR + k0l + 2 * tg;
                af[mi][0] = *(const uint32_t*)(p);
                af[mi][1] = *(const uint32_t*)(p + 8 * G2_ASTR);
                af[mi][2] = *(const uint32_t*)(p + 8);
                af[mi][3] = *(const uint32_t*)(p + 8 * G2_ASTR + 8);
            }
            #pragma unroll
            for (int mi = 0; mi < 2; mi++)
                #pragma unroll
                for (int ni = 0; ni < 5; ni++) {
                    MMA16816(acc[mi][ni], af[mi], bh[ni]);
                    MMA16816(acc[mi][ni], af[mi], bl[ni]);
                }
            #pragma unroll
            for (int mi = 0; mi < 2; mi++) {
                const __nv_bfloat16* p = AL + (wid * 32 + mi * 16 + g) * G2_ASTR + k0l + 2 * tg;
                af[mi][0] = *(const uint32_t*)(p);
                af[mi][1] = *(const uint32_t*)(p + 8 * G2_ASTR);
                af[mi][2] = *(const uint32_t*)(p + 8);
                af[mi][3] = *(const uint32_t*)(p + 8 * G2_ASTR + 8);
            }
            #pragma unroll
            for (int mi = 0; mi < 2; mi++)
                #pragma unroll
                for (int ni = 0; ni < 5; ni++)
                    MMA16816(acc[mi][ni], af[mi], bh[ni]);
        }
        __syncthreads();
    }

    #pragma unroll
    for (int mi = 0; mi < 2; mi++) {
        #pragma unroll
        for (int half = 0; half < 2; half++) {
            int row = m0 + wid * 32 + mi * 16 + g + half * 8;
            if (row < NN) {
                float di = g_dinv[row];
                #pragma unroll
                for (int ni = 0; ni < 5; ni++) {
                    float2 o;
                    o.x = acc[mi][ni][half * 2]     * di;
                    o.y = acc[mi][ni][half * 2 + 1] * di;
                    *(float2*)(g_h2t + (size_t)row * OUTD + ni * 8 + 2 * tg) = o;
                }
            }
        }
    }
}

// ---------------- agg2 + bias + log_softmax ----------------
__global__ __launch_bounds__(256) void k_agg2(const float* __restrict__ b2,
                                              float* __restrict__ out) {
    int gw = (blockIdx.x * 256 + threadIdx.x) >> 5;
    int lane = threadIdx.x & 31;
    if (gw >= NN) return;
    bool hi = lane < 8;

    const float* self = g_h2t + (size_t)gw * OUTD;
    float a0 = self[lane];
    float a1v = hi ? self[32 + lane] : 0.f;

    int beg = g_rowptr[gw], end = g_rowptr[gw + 1];
    for (int e = beg; e < end; e++) {
        int s = g_col[e];
        const float* p = g_h2t + (size_t)s * OUTD;
        a0 += p[lane];
        if (hi) a1v += p[32 + lane];
    }

    float di = g_dinv[gw];
    float z0 = fmaf(di, a0, b2[lane]);
    float z1 = hi ? fmaf(di, a1v, b2[32 + lane]) : -3.4e38f;

    float mx = fmaxf(z0, z1);
    #pragma unroll
    for (int d = 16; d; d >>= 1) mx = fmaxf(mx, __shfl_xor_sync(0xffffffffu, mx, d));
    float s0 = expf(z0 - mx) + (hi ? expf(z1 - mx) : 0.f);
    #pragma unroll
    for (int d = 16; d; d >>= 1) s0 += __shfl_xor_sync(0xffffffffu, s0, d);
    float lse = mx + logf(s0);

    out[(size_t)gw * OUTD + lane] = z0 - lse;
    if (hi) out[(size_t)gw * OUTD + 32 + lane] = z1 - lse;
}

// ---------------- launch ----------------
extern "C" void kernel_launch(void* const* d_in, const int* in_sizes, int n_in,
                              void* d_out, int out_size) {
    const float* x  = (const float*)d_in[0];
    const int*   ei = (const int*)d_in[1];
    const float* W1 = (const float*)d_in[2];
    const float* b1 = (const float*)d_in[3];
    const float* W2 = (const float*)d_in[4];
    const float* b2 = (const float*)d_in[5];
    const int* src = ei;
    const int* dst = ei + NE;
    float* out = (float*)d_out;

    // Idempotent, capture-safe (not stream ops); no static guard per harness rules.
    cudaFuncSetAttribute(k_gemm1_mma, cudaFuncAttributeMaxDynamicSharedMemorySize, G1_SMEM);
    cudaFuncSetAttribute(k_gemm2_mma, cudaFuncAttributeMaxDynamicSharedMemorySize, G2_SMEM);

    k_init<<<(NN + 255) / 256, 256>>>(W1, W2);
    k_count<<<(NE + 255) / 256, 256>>>(dst);
    k_scanf<<<NB1, 1024>>>();
    k_fill<<<(NE + 255) / 256, 256>>>(src, dst);

    k_aggx<<<(NN * 32 + 255) / 256, 256>>>(x);
    k_gemm1_mma<<<dim3((NN + 127) / 128, 2), 256, G1_SMEM>>>(b1);
    k_gemm2_mma<<<(NN + 255) / 256, 256, G2_SMEM>>>();
    k_agg2<<<(NN * 32 + 255) / 256, 256>>>(b2, out);
}

// round 16
// speedup vs baseline: 1.1985x; 1.1723x over previous
#include <cuda_runtime.h>
#include <cuda_bf16.h>
#include <cstdint>

#define NN   100000
#define NE   800000
#define IND  128
#define HID  256
#define OUTD 40
#define NB1  98   // blocks in persistent CSR kernel (< 148 SMs => co-resident)

// ---------------- scratch (static __device__ per harness rules) ----------------
__device__ int   g_cnt[NN];
__device__ int   g_rowptr[NN + 1];
__device__ int   g_cursor[NN];
__device__ int   g_col[NE];
__device__ float g_dinv[NN];
__device__ int   g_bsum[NB1];
__device__ int   g_arr1, g_arr2, g_arr3;
__device__ __nv_bfloat16 g_xah[(size_t)NN * IND];   // aggregated input, bf16 hi
__device__ __nv_bfloat16 g_xal[(size_t)NN * IND];   // aggregated input, bf16 lo
__device__ __nv_bfloat16 g_w1th[(size_t)HID * IND]; // W1^T [n][k] bf16 hi
__device__ __nv_bfloat16 g_w1tl[(size_t)HID * IND]; // W1^T [n][k] bf16 lo
__device__ __nv_bfloat16 g_w2th[(size_t)OUTD * HID]; // W2^T [n][k] bf16 hi
__device__ __nv_bfloat16 g_w2tl[(size_t)OUTD * HID]; // W2^T [n][k] bf16 lo
__device__ float g_h2t[(size_t)NN * OUTD]; // (a1@W2)*dinv[row]

// ---------------- fused init: zero counters + W1/W2 transpose-split ----------
__global__ __launch_bounds__(256) void k_init(const float* __restrict__ W1,
                                              const float* __restrict__ W2) {
    int i = blockIdx.x * 256 + threadIdx.x;
    if (i < NN) g_cnt[i] = 0;
    if (i == 0) { g_arr1 = 0; g_arr2 = 0; g_arr3 = 0; }
    if (i < HID * IND) {                        // 32768: W1 transpose+split
        int n = i & 255, k = i >> 8;
        float v = W1[(size_t)k * HID + n];
        __nv_bfloat16 h = __float2bfloat16(v);
        g_w1th[(size_t)n * IND + k] = h;
        g_w1tl[(size_t)n * IND + k] = __float2bfloat16(v - __bfloat162float(h));
    }
    if (i < OUTD * HID) {                       // 10240: W2 transpose+split
        int k = i & 255, n = i >> 8;
        float v = W2[(size_t)k * OUTD + n];
        __nv_bfloat16 h = __float2bfloat16(v);
        g_w2th[(size_t)n * HID + k] = h;
        g_w2tl[(size_t)n * HID + k] = __float2bfloat16(v - __bfloat162float(h));
    }
}

// ---------------- persistent CSR build: count -> scan -> fill ----------------
// 98 co-resident blocks, grid handshakes between phases. 8 unrolled edges per
// thread => 8 independent atomic chains in flight (hides 318-cyc ATOMG).
__global__ __launch_bounds__(1024) void k_csr(const int* __restrict__ src,
                                              const int* __restrict__ dst) {
    const int b = blockIdx.x, t = threadIdx.x;
    const int lane = t & 31, wid = t >> 5;
    const int base = b * 1024 + t;
    const int gstride = NB1 * 1024;             // 100352

    // ---- phase 1: degree count ----
    #pragma unroll
    for (int j = 0; j < 8; j++) {
        int e = base + j * gstride;
        if (e < NE) atomicAdd(&g_cnt[__ldg(dst + e)], 1);
    }
    if (t == 0) {
        __threadfence();
        atomicAdd(&g_arr1, 1);
        while (atomicAdd(&g_arr1, 0) < NB1) { }
    }
    __syncthreads();

    // ---- phase 2: exclusive scan over g_cnt ----
    const int i = base;
    int c = (i < NN) ? g_cnt[i] : 0;
    int v = c;
    #pragma unroll
    for (int d = 1; d < 32; d <<= 1) {
        int tt = __shfl_up_sync(0xffffffffu, v, d);
        if (lane >= d) v += tt;
    }
    __shared__ int ws[32];
    if (lane == 31) ws[wid] = v;
    __syncthreads();
    if (wid == 0) {
        int w = ws[lane];
        #pragma unroll
        for (int d = 1; d < 32; d <<= 1) {
            int tt = __shfl_up_sync(0xffffffffu, w, d);
            if (lane >= d) w += tt;
        }
        ws[lane] = w;
    }
    __syncthreads();
    const int woff = wid ? ws[wid - 1] : 0;
    const int incl = v + woff;
    const int btotal = ws[31];

    if (t == 0) {
        g_bsum[b] = btotal;
        __threadfence();
        atomicAdd(&g_arr2, 1);
        while (atomicAdd(&g_arr2, 0) < NB1) { }
    }
    __syncthreads();

    __shared__ int sm[NB1];
    __shared__ int boffs;
    if (t < NB1) sm[t] = g_bsum[t];
    __syncthreads();
    if (t == 0) {
        int run = 0;
        for (int j = 0; j < b; j++) run += sm[j];
        boffs = run;
        if (b == NB1 - 1) g_rowptr[NN] = run + btotal;
    }
    __syncthreads();

    if (i < NN) {
        int excl = incl - c + boffs;
        g_rowptr[i] = excl;
        g_cursor[i] = excl;
        g_dinv[i]   = rsqrtf((float)(c + 1));  // +1 self-loop, deg >= 1
    }

    if (t == 0) {
        __threadfence();
        atomicAdd(&g_arr3, 1);
        while (atomicAdd(&g_arr3, 0) < NB1) { }
    }
    __syncthreads();

    // ---- phase 3: fill adjacency ----
    #pragma unroll
    for (int j = 0; j < 8; j++) {
        int e = base + j * gstride;
        if (e < NE) {
            int d = __ldg(dst + e);
            int p = atomicAdd(&g_cursor[d], 1);
            g_col[p] = __ldg(src + e);
        }
    }
}

// ---------------- aggX: xa[d]=dinv[d]*(sum dinv[s]x[s] + dinv[d]x[d]), bf16 split out --
__global__ __launch_bounds__(256) void k_aggx(const float* __restrict__ x) {
    int gw = (blockIdx.x * 256 + threadIdx.x) >> 5;
    int lane = threadIdx.x & 31;
    if (gw >= NN) return;

    const float4* x4 = (const float4*)x;
    float dg = g_dinv[gw];
    float4 xs = x4[(size_t)gw * 32 + lane];
    float4 acc;
    acc.x = dg * xs.x; acc.y = dg * xs.y; acc.z = dg * xs.z; acc.w = dg * xs.w;

    int beg = g_rowptr[gw], end = g_rowptr[gw + 1];
    for (int e = beg; e < end; e++) {
        int s = g_col[e];
        float ds = g_dinv[s];
        float4 v = x4[(size_t)s * 32 + lane];
        acc.x = fmaf(ds, v.x, acc.x);
        acc.y = fmaf(ds, v.y, acc.y);
        acc.z = fmaf(ds, v.z, acc.z);
        acc.w = fmaf(ds, v.w, acc.w);
    }

    float ox = dg * acc.x, oy = dg * acc.y, oz = dg * acc.z, ow = dg * acc.w;
    __nv_bfloat16 hx = __float2bfloat16(ox), hy = __float2bfloat16(oy);
    __nv_bfloat16 hz = __float2bfloat16(oz), hw = __float2bfloat16(ow);
    __nv_bfloat162 h01, h23, l01, l23;
    h01.x = hx; h01.y = hy; h23.x = hz; h23.y = hw;
    l01.x = __float2bfloat16(ox - __bfloat162float(hx));
    l01.y = __float2bfloat16(oy - __bfloat162float(hy));
    l23.x = __float2bfloat16(oz - __bfloat162float(hz));
    l23.y = __float2bfloat16(ow - __bfloat162float(hw));
    size_t base = (size_t)gw * IND + lane * 4;
    *(__nv_bfloat162*)(g_xah + base)     = h01;
    *(__nv_bfloat162*)(g_xah + base + 2) = h23;
    *(__nv_bfloat162*)(g_xal + base)     = l01;
    *(__nv_bfloat162*)(g_xal + base + 2) = l23;
}

#define MMA16816(c, a, b)                                                       \
    asm volatile("mma.sync.aligned.m16n8k16.row.col.f32.bf16.bf16.f32 "         \
        "{%0,%1,%2,%3}, {%4,%5,%6,%7}, {%8,%9}, {%0,%1,%2,%3};"                 \
        : "+f"((c)[0]), "+f"((c)[1]), "+f"((c)[2]), "+f"((c)[3])                \
        : "r"((a)[0]), "r"((a)[1]), "r"((a)[2]), "r"((a)[3]),                   \
          "r"((b)[0]), "r"((b)[1]))

// ---------------- FUSED GEMM: a1 = relu(xa@W1+b1) in SMEM, then h2t = (a1@W2)*dinv --
// Phase 1: per-CTA 128 rows x full N=256 (two 128-col halves), split-bf16 mma;
//          epilogue writes a1 hi/lo into SMEM (stride 264).
// Phase 2: W2^T hi/lo into dead stage region; gemm2 mma straight from SMEM.
#define F_STRIDE 72                               // stage stride (64+8)
#define F_ARR    (128 * F_STRIDE)                 // 9216 bf16
#define F_A1STR  264                              // a1 stride (256+8)
#define F_A1H    (4 * F_ARR)                      // 36864
#define F_A1L    (F_A1H + 128 * F_A1STR)          // 70656
#define F_TOTAL  ((F_A1L + 128 * F_A1STR) * 2)    // 208896 bytes

__global__ __launch_bounds__(256, 1) void k_fused(const float* __restrict__ b1) {
    extern __shared__ __nv_bfloat16 smb[];
    __nv_bfloat16* AH  = smb;
    __nv_bfloat16* AL  = smb + F_ARR;
    __nv_bfloat16* BH  = smb + 2 * F_ARR;
    __nv_bfloat16* BL  = smb + 3 * F_ARR;
    __nv_bfloat16* A1H = smb + F_A1H;
    __nv_bfloat16* A1L = smb + F_A1L;
    __nv_bfloat16* W2H = smb;                     // aliases stage region (phase 2)
    __nv_bfloat16* W2L = smb + OUTD * F_A1STR;    // 10560

    const int tid = threadIdx.x;
    const int wid = tid >> 5, lane = tid & 31;
    const int g = lane >> 2, tg = lane & 3;
    const int wm = wid >> 2, wn = wid & 3;
    const int m0 = blockIdx.x * 128;

    // ================= phase 1: layer-1 GEMM, full N =================
    for (int hn = 0; hn < 2; hn++) {
        const int n0 = hn << 7;
        float acc[4][4][4];
        #pragma unroll
        for (int mi = 0; mi < 4; mi++)
            #pragma unroll
            for (int ni = 0; ni < 4; ni++)
                #pragma unroll
                for (int q = 0; q < 4; q++) acc[mi][ni][q] = 0.f;

        for (int kc = 0; kc < 2; kc++) {
            #pragma unroll
            for (int i = 0; i < 4; i++) {
                int idx = tid + i * 256;
                int r = idx >> 3, c8 = idx & 7;
                size_t goff = (size_t)(m0 + r) * IND + kc * 64 + c8 * 8;
                uint4 z = make_uint4(0, 0, 0, 0);
                bool ok = (m0 + r) < NN;
                *(uint4*)(AH + r * F_STRIDE + c8 * 8) = ok ? *(const uint4*)(g_xah + goff) : z;
                *(uint4*)(AL + r * F_STRIDE + c8 * 8) = ok ? *(const uint4*)(g_xal + goff) : z;
                size_t boff = (size_t)(n0 + r) * IND + kc * 64 + c8 * 8;
                *(uint4*)(BH + r * F_STRIDE + c8 * 8) = *(const uint4*)(g_w1th + boff);
                *(uint4*)(BL + r * F_STRIDE + c8 * 8) = *(const uint4*)(g_w1tl + boff);
            }
            __syncthreads();

            #pragma unroll
            for (int ks = 0; ks < 4; ks++) {
                int k0 = ks * 16;
                uint32_t af[4][4], bh[4][2], bl[4][2];
                #pragma unroll
                for (int ni = 0; ni < 4; ni++) {
                    const __nv_bfloat16* p = BH + (wn * 32 + ni * 8 + g) * F_STRIDE + k0 + 2 * tg;
                    bh[ni][0] = *(const uint32_t*)(p);
                    bh[ni][1] = *(const uint32_t*)(p + 8);
                    const __nv_bfloat16* q = BL + (wn * 32 + ni * 8 + g) * F_STRIDE + k0 + 2 * tg;
                    bl[ni][0] = *(const uint32_t*)(q);
                    bl[ni][1] = *(const uint32_t*)(q + 8);
                }
                #pragma unroll
                for (int mi = 0; mi < 4; mi++) {
                    const __nv_bfloat16* p = AH + (wm * 64 + mi * 16 + g) * F_STRIDE + k0 + 2 * tg;
                    af[mi][0] = *(const uint32_t*)(p);
                    af[mi][1] = *(const uint32_t*)(p + 8 * F_STRIDE);
                    af[mi][2] = *(const uint32_t*)(p + 8);
                    af[mi][3] = *(const uint32_t*)(p + 8 * F_STRIDE + 8);
                }
                #pragma unroll
                for (int mi = 0; mi < 4; mi++)
                    #pragma unroll
                    for (int ni = 0; ni < 4; ni++) {
                        MMA16816(acc[mi][ni], af[mi], bh[ni]);
                        MMA16816(acc[mi][ni], af[mi], bl[ni]);
                    }
                #pragma unroll
                for (int mi = 0; mi < 4; mi++) {
                    const __nv_bfloat16* p = AL + (wm * 64 + mi * 16 + g) * F_STRIDE + k0 + 2 * tg;
                    af[mi][0] = *(const uint32_t*)(p);
                    af[mi][1] = *(const uint32_t*)(p + 8 * F_STRIDE);
                    af[mi][2] = *(const uint32_t*)(p + 8);
                    af[mi][3] = *(const uint32_t*)(p + 8 * F_STRIDE + 8);
                }
                #pragma unroll
                for (int mi = 0; mi < 4; mi++)
                    #pragma unroll
                    for (int ni = 0; ni < 4; ni++)
                        MMA16816(acc[mi][ni], af[mi], bh[ni]);
            }
            __syncthreads();
        }

        // ---- epilogue: bias + relu -> bf16 hi/lo into SMEM a1 ----
        #pragma unroll
        for (int ni = 0; ni < 4; ni++) {
            int coll = wn * 32 + ni * 8 + 2 * tg;
            float bz0 = __ldg(b1 + n0 + coll), bz1 = __ldg(b1 + n0 + coll + 1);
            #pragma unroll
            for (int mi = 0; mi < 4; mi++) {
                #pragma unroll
                for (int half = 0; half < 2; half++) {
                    int rloc = wm * 64 + mi * 16 + g + half * 8;
                    float v0 = fmaxf(acc[mi][ni][half * 2]     + bz0, 0.f);
                    float v1 = fmaxf(acc[mi][ni][half * 2 + 1] + bz1, 0.f);
                    __nv_bfloat16 h0 = __float2bfloat16(v0);
                    __nv_bfloat16 h1 = __float2bfloat16(v1);
                    __nv_bfloat162 hh, ll;
                    hh.x = h0; hh.y = h1;
                    ll.x = __float2bfloat16(v0 - __bfloat162float(h0));
                    ll.y = __float2bfloat16(v1 - __bfloat162float(h1));
                    int off = rloc * F_A1STR + n0 + coll;
                    *(__nv_bfloat162*)(A1H + off) = hh;
                    *(__nv_bfloat162*)(A1L + off) = ll;
                }
            }
        }
        __syncthreads();
    }

    // ================= phase 2: layer-2 GEMM from SMEM =================
    #pragma unroll
    for (int i = 0; i < 5; i++) {
        int idx = tid + i * 256;                 // 0..1279
        int r = idx >> 5, c8 = idx & 31;
        size_t goff = (size_t)r * HID + c8 * 8;
        *(uint4*)(W2H + r * F_A1STR + c8 * 8) = *(const uint4*)(g_w2th + goff);
        *(uint4*)(W2L + r * F_A1STR + c8 * 8) = *(const uint4*)(g_w2tl + goff);
    }
    __syncthreads();

    float acc2[5][4];
    #pragma unroll
    for (int ni = 0; ni < 5; ni++)
        #pragma unroll
        for (int q = 0; q < 4; q++) acc2[ni][q] = 0.f;

    #pragma unroll
    for (int ks = 0; ks < 16; ks++) {
        int k0 = ks * 16;
        uint32_t afh[4], afl[4], bh[5][2], bl[5][2];
        #pragma unroll
        for (int ni = 0; ni < 5; ni++) {
            const __nv_bfloat16* p = W2H + (ni * 8 + g) * F_A1STR + k0 + 2 * tg;
            bh[ni][0] = *(const uint32_t*)(p);
            bh[ni][1] = *(const uint32_t*)(p + 8);
            const __nv_bfloat16* q = W2L + (ni * 8 + g) * F_A1STR + k0 + 2 * tg;
            bl[ni][0] = *(const uint32_t*)(q);
            bl[ni][1] = *(const uint32_t*)(q + 8);
        }
        {
            const __nv_bfloat16* p = A1H + (wid * 16 + g) * F_A1STR + k0 + 2 * tg;
            afh[0] = *(const uint32_t*)(p);
            afh[1] = *(const uint32_t*)(p + 8 * F_A1STR);
            afh[2] = *(const uint32_t*)(p + 8);
            afh[3] = *(const uint32_t*)(p + 8 * F_A1STR + 8);
            const __nv_bfloat16* q = A1L + (wid * 16 + g) * F_A1STR + k0 + 2 * tg;
            afl[0] = *(const uint32_t*)(q);
            afl[1] = *(const uint32_t*)(q + 8 * F_A1STR);
            afl[2] = *(const uint32_t*)(q + 8);
            afl[3] = *(const uint32_t*)(q + 8 * F_A1STR + 8);
        }
        #pragma unroll
        for (int ni = 0; ni < 5; ni++) {
            MMA16816(acc2[ni], afh, bh[ni]);
            MMA16816(acc2[ni], afh, bl[ni]);
            MMA16816(acc2[ni], afl, bh[ni]);
        }
    }

    #pragma unroll
    for (int half = 0; half < 2; half++) {
        int row = m0 + wid * 16 + g + half * 8;
        if (row < NN) {
            float di = g_dinv[row];
            #pragma unroll
            for (int ni = 0; ni < 5; ni++) {
                float2 o;
                o.x = acc2[ni][half * 2]     * di;
                o.y = acc2[ni][half * 2 + 1] * di;
                *(float2*)(g_h2t + (size_t)row * OUTD + ni * 8 + 2 * tg) = o;
            }
        }
    }
}

// ---------------- agg2 + bias + log_softmax ----------------
__global__ __launch_bounds__(256) void k_agg2(const float* __restrict__ b2,
                                              float* __restrict__ out) {
    int gw = (blockIdx.x * 256 + threadIdx.x) >> 5;
    int lane = threadIdx.x & 31;
    if (gw >= NN) return;
    bool hi = lane < 8;

    const float* self = g_h2t + (size_t)gw * OUTD;
    float a0 = self[lane];
    float a1v = hi ? self[32 + lane] : 0.f;

    int beg = g_rowptr[gw], end = g_rowptr[gw + 1];
    for (int e = beg; e < end; e++) {
        int s = g_col[e];
        const float* p = g_h2t + (size_t)s * OUTD;
        a0 += p[lane];
        if (hi) a1v += p[32 + lane];
    }

    float di = g_dinv[gw];
    float z0 = fmaf(di, a0, b2[lane]);
    float z1 = hi ? fmaf(di, a1v, b2[32 + lane]) : -3.4e38f;

    float mx = fmaxf(z0, z1);
    #pragma unroll
    for (int d = 16; d; d >>= 1) mx = fmaxf(mx, __shfl_xor_sync(0xffffffffu, mx, d));
    float s0 = expf(z0 - mx) + (hi ? expf(z1 - mx) : 0.f);
    #pragma unroll
    for (int d = 16; d; d >>= 1) s0 += __shfl_xor_sync(0xffffffffu, s0, d);
    float lse = mx + logf(s0);

    out[(size_t)gw * OUTD + lane] = z0 - lse;
    if (hi) out[(size_t)gw * OUTD + 32 + lane] = z1 - lse;
}

// ---------------- launch ----------------
extern "C" void kernel_launch(void* const* d_in, const int* in_sizes, int n_in,
                              void* d_out, int out_size) {
    const float* x  = (const float*)d_in[0];
    const int*   ei = (const int*)d_in[1];
    const float* W1 = (const float*)d_in[2];
    const float* b1 = (const float*)d_in[3];
    const float* W2 = (const float*)d_in[4];
    const float* b2 = (const float*)d_in[5];
    const int* src = ei;
    const int* dst = ei + NE;
    float* out = (float*)d_out;

    // Idempotent, capture-safe (not a stream op); no static guard per harness rules.
    cudaFuncSetAttribute(k_fused, cudaFuncAttributeMaxDynamicSharedMemorySize, F_TOTAL);

    k_init<<<(NN + 255) / 256, 256>>>(W1, W2);
    k_csr<<<NB1, 1024>>>(src, dst);
    k_aggx<<<(NN * 32 + 255) / 256, 256>>>(x);
    k_fused<<<(NN + 127) / 128, 256, F_TOTAL>>>(b1);
    k_agg2<<<(NN * 32 + 255) / 256, 256>>>(b2, out);
}